// round 2
// baseline (speedup 1.0000x reference)
#include <cuda_runtime.h>
#include <math.h>

// ---------------- problem constants ----------------
#define B_    2
#define N_    2048
#define DIM_  1024
#define H_    16
#define DH_   64
#define NNK_  2
#define J_    (N_ + NNK_)    // 2050
#define SCALE_ 8.0f

// ---------------- scratch (device globals; no allocs allowed) ----------------
__device__ float g_xn [B_ * N_ * DIM_];        // layernormed x
__device__ float g_q  [B_ * N_ * DIM_];        // q projection (b,n,h*dh)
__device__ float g_kv [B_ * N_ * 2 * DIM_];    // kv projection (b,n,2*h*dh)
__device__ float g_Qn [B_ * H_ * N_ * DH_];    // l2norm'd q, (b,h,n,d)
__device__ float g_K  [B_ * H_ * J_ * DH_];    // l2norm'd k incl nulls, (b,h,j,d)
__device__ float g_V  [B_ * H_ * J_ * DH_];    // v incl nulls, (b,h,j,d)
__device__ float g_att[B_ * N_ * DIM_];        // attention output (b,n,h*dh)

// ---------------- LayerNorm ----------------
__global__ void ln_kernel(const float* __restrict__ x,
                          const float* __restrict__ gamma,
                          float* __restrict__ xn) {
    int row = blockIdx.x;                       // 0..B*N-1
    const float* xr = x + (size_t)row * DIM_;
    float v[4];
    float s = 0.f, sq = 0.f;
#pragma unroll
    for (int i = 0; i < 4; i++) {
        float t = xr[threadIdx.x + i * 256];
        v[i] = t; s += t; sq += t * t;
    }
#pragma unroll
    for (int off = 16; off > 0; off >>= 1) {
        s  += __shfl_xor_sync(0xffffffffu, s,  off);
        sq += __shfl_xor_sync(0xffffffffu, sq, off);
    }
    __shared__ float sa[8], sb[8];
    int w = threadIdx.x >> 5, l = threadIdx.x & 31;
    if (l == 0) { sa[w] = s; sb[w] = sq; }
    __syncthreads();
    if (threadIdx.x == 0) {
        float a = 0.f, bq = 0.f;
#pragma unroll
        for (int i = 0; i < 8; i++) { a += sa[i]; bq += sb[i]; }
        sa[0] = a; sb[0] = bq;
    }
    __syncthreads();
    float mean = sa[0] * (1.0f / DIM_);
    float var  = sb[0] * (1.0f / DIM_) - mean * mean;
    float rstd = rsqrtf(var + 1e-5f);
    float* outr = xn + (size_t)row * DIM_;
#pragma unroll
    for (int i = 0; i < 4; i++) {
        int d = threadIdx.x + i * 256;
        outr[d] = (v[i] - mean) * rstd * gamma[d];
    }
}

// ---------------- SGEMM: C[M,N] = A[M,K] @ B[K,N], all row-major ----------------
// 128x128 tile, BK=8, 256 threads, 8x8 per thread (split 4+4 for bank-friendly float4).
__global__ void __launch_bounds__(256) sgemm128(
        const float* __restrict__ A, const float* __restrict__ B,
        float* __restrict__ C, int M, int N, int K) {
    __shared__ float As[8][128];
    __shared__ float Bs[8][128];
    const int tid = threadIdx.x;
    const int bx = blockIdx.x, by = blockIdx.y;
    const int row0 = by * 128, col0 = bx * 128;
    const int tx = tid & 15, ty = tid >> 4;
    const int a_row = tid >> 1, a_col = (tid & 1) << 2;   // A loader: 128x8 via float4
    const int b_row = tid >> 5, b_col = (tid & 31) << 2;  // B loader: 8x128 via float4

    float acc[8][8];
#pragma unroll
    for (int i = 0; i < 8; i++)
#pragma unroll
        for (int j = 0; j < 8; j++) acc[i][j] = 0.f;

    const float* Aptr = A + (size_t)(row0 + a_row) * K + a_col;
    const float* Bptr = B + (size_t)b_row * N + col0 + b_col;

    for (int kt = 0; kt < K; kt += 8) {
        float4 av = *(const float4*)(Aptr + kt);
        As[a_col + 0][a_row] = av.x;
        As[a_col + 1][a_row] = av.y;
        As[a_col + 2][a_row] = av.z;
        As[a_col + 3][a_row] = av.w;
        float4 bv = *(const float4*)(Bptr + (size_t)kt * N);
        *(float4*)&Bs[b_row][b_col] = bv;
        __syncthreads();
#pragma unroll
        for (int k = 0; k < 8; k++) {
            float ar[8], br[8];
            *(float4*)(ar)     = *(const float4*)&As[k][ty * 4];
            *(float4*)(ar + 4) = *(const float4*)&As[k][ty * 4 + 64];
            *(float4*)(br)     = *(const float4*)&Bs[k][tx * 4];
            *(float4*)(br + 4) = *(const float4*)&Bs[k][tx * 4 + 64];
#pragma unroll
            for (int i = 0; i < 8; i++)
#pragma unroll
                for (int j = 0; j < 8; j++)
                    acc[i][j] += ar[i] * br[j];
        }
        __syncthreads();
    }
#pragma unroll
    for (int i = 0; i < 8; i++) {
        int r = row0 + ((i < 4) ? (ty * 4 + i) : (64 + ty * 4 + i - 4));
        float* Crow = C + (size_t)r * N + col0;
        float4 o0 = { acc[i][0], acc[i][1], acc[i][2], acc[i][3] };
        float4 o1 = { acc[i][4], acc[i][5], acc[i][6], acc[i][7] };
        *(float4*)(Crow + tx * 4)      = o0;
        *(float4*)(Crow + tx * 4 + 64) = o1;
    }
}

// ---------------- prep: build Qn (l2norm*q_scale), K (nulls + l2norm*k_scale), V ----------------
__global__ void prep_kernel(const float* __restrict__ q,
                            const float* __restrict__ kv,
                            const float* __restrict__ null_kv,
                            const float* __restrict__ q_scale,
                            const float* __restrict__ k_scale,
                            float* __restrict__ Qn,
                            float* __restrict__ Kk,
                            float* __restrict__ Vv) {
    int warp = (blockIdx.x * blockDim.x + threadIdx.x) >> 5;
    int lane = threadIdx.x & 31;
    if (warp >= B_ * H_ * J_) return;
    int bh = warp / J_;
    int j  = warp % J_;
    int b = bh / H_, h = bh % H_;
    int d0 = lane, d1 = lane + 32;

    float k0, k1, v0, v1;
    if (j < NNK_) {
        // null_kv reshape (H, NNK, 2, DH): [((h*NNK + j)*2 + s)*DH + d]
        const float* nb = null_kv + ((size_t)(h * NNK_ + j) * 2) * DH_;
        k0 = nb[d0];        k1 = nb[d1];
        v0 = nb[DH_ + d0];  v1 = nb[DH_ + d1];
    } else {
        int n = j - NNK_;
        const float* base = kv + ((size_t)(b * N_ + n)) * (2 * DIM_) + h * DH_;
        k0 = base[d0];          k1 = base[d1];
        v0 = base[DIM_ + d0];   v1 = base[DIM_ + d1];
    }
    float ss = k0 * k0 + k1 * k1;
#pragma unroll
    for (int off = 16; off > 0; off >>= 1)
        ss += __shfl_xor_sync(0xffffffffu, ss, off);
    float inv = 1.0f / fmaxf(sqrtf(ss), 1e-12f);
    size_t kvo = ((size_t)bh * J_ + j) * DH_;
    Kk[kvo + d0] = k0 * inv * k_scale[d0];
    Kk[kvo + d1] = k1 * inv * k_scale[d1];
    Vv[kvo + d0] = v0;
    Vv[kvo + d1] = v1;

    if (j < N_) {
        int n = j;
        const float* qb = q + ((size_t)(b * N_ + n)) * DIM_ + h * DH_;
        float a0 = qb[d0], a1 = qb[d1];
        float qs2 = a0 * a0 + a1 * a1;
#pragma unroll
        for (int off = 16; off > 0; off >>= 1)
            qs2 += __shfl_xor_sync(0xffffffffu, qs2, off);
        float qinv = 1.0f / fmaxf(sqrtf(qs2), 1e-12f);
        size_t qo = ((size_t)bh * N_ + n) * DH_;
        Qn[qo + d0] = a0 * qinv * q_scale[d0];
        Qn[qo + d1] = a1 * qinv * q_scale[d1];
    }
}

// ---------------- flash attention: 64x64 tiles, online softmax, causal skip ----------------
#define SPAD 68
__global__ void __launch_bounds__(256) attn_kernel(
        const float* __restrict__ Qn, const float* __restrict__ Kk,
        const float* __restrict__ Vv, const float* __restrict__ bias,
        const int* __restrict__ mask,
        float* __restrict__ att) {
    extern __shared__ float sh[];
    float* Qs  = sh;                 // [64][SPAD]  Qs[i][d]
    float* KsT = Qs  + 64 * SPAD;    // [64][SPAD]  KsT[d][j]
    float* Vs  = KsT + 64 * SPAD;    // [64][SPAD]  Vs[j][d]
    float* Ss  = Vs  + 64 * SPAD;    // [64][SPAD]  P[i][j]

    const int tid = threadIdx.x;
    const int tx = tid & 15, ty = tid >> 4;
    const int ib = blockIdx.x;
    const int bh = blockIdx.y;
    const int b = bh >> 4, h = bh & 15;
    const int i0 = ib * 64;

    // load Q tile once
    const float* Qbase = Qn + ((size_t)bh * N_ + i0) * DH_;
#pragma unroll
    for (int fi = tid; fi < 64 * 16; fi += 256) {
        int r = fi >> 4, c4 = (fi & 15) << 2;
        *(float4*)&Qs[r * SPAD + c4] = *(const float4*)(Qbase + (size_t)r * DH_ + c4);
    }

    float m[4], lsum[4], acc[4][4];
#pragma unroll
    for (int r = 0; r < 4; r++) {
        m[r] = -1e30f; lsum[r] = 0.f;
#pragma unroll
        for (int c = 0; c < 4; c++) acc[r][c] = 0.f;
    }

    const int jt_max = min(ib + 1, (J_ + 63) / 64 - 1);   // causal: skip tiles above diag

    for (int jt = 0; jt <= jt_max; jt++) {
        const int j0 = jt * 64;
        __syncthreads();   // protect KsT/Vs/Ss from prior-iter reads (and Qs writes, iter 0)
        // load K (transposed) and V tiles
        for (int fi = tid; fi < 64 * 16; fi += 256) {
            int r = fi >> 4, c4 = (fi & 15) << 2;
            int j = j0 + r;
            if (j < J_) {
                float4 k4 = *(const float4*)(Kk + ((size_t)bh * J_ + j) * DH_ + c4);
                KsT[(c4 + 0) * SPAD + r] = k4.x;
                KsT[(c4 + 1) * SPAD + r] = k4.y;
                KsT[(c4 + 2) * SPAD + r] = k4.z;
                KsT[(c4 + 3) * SPAD + r] = k4.w;
                *(float4*)&Vs[r * SPAD + c4] =
                    *(const float4*)(Vv + ((size_t)bh * J_ + j) * DH_ + c4);
            } else {
                KsT[(c4 + 0) * SPAD + r] = 0.f;
                KsT[(c4 + 1) * SPAD + r] = 0.f;
                KsT[(c4 + 2) * SPAD + r] = 0.f;
                KsT[(c4 + 3) * SPAD + r] = 0.f;
                float4 z = {0.f, 0.f, 0.f, 0.f};
                *(float4*)&Vs[r * SPAD + c4] = z;
            }
        }
        __syncthreads();

        // S = Q @ K^T (4x4 per thread)
        float s[4][4];
#pragma unroll
        for (int r = 0; r < 4; r++)
#pragma unroll
            for (int c = 0; c < 4; c++) s[r][c] = 0.f;

#pragma unroll 4
        for (int d = 0; d < 64; d++) {
            float qr[4];
#pragma unroll
            for (int r = 0; r < 4; r++) qr[r] = Qs[(ty * 4 + r) * SPAD + d];
            float4 k4 = *(const float4*)&KsT[d * SPAD + tx * 4];
            float kr[4] = { k4.x, k4.y, k4.z, k4.w };
#pragma unroll
            for (int r = 0; r < 4; r++)
#pragma unroll
                for (int c = 0; c < 4; c++)
                    s[r][c] += qr[r] * kr[c];
        }

        // scale + bias + masks
#pragma unroll
        for (int r = 0; r < 4; r++) {
            int ig = i0 + ty * 4 + r;
#pragma unroll
            for (int c = 0; c < 4; c++) {
                int jg = j0 + tx * 4 + c;
                float val = s[r][c] * SCALE_;
                bool ok = (jg < J_) && (jg <= ig + NNK_);
                if (jg >= NNK_ && ok) {
                    val += bias[((size_t)h * N_ + ig) * N_ + (jg - NNK_)];
                    ok = (mask[b * N_ + jg - NNK_] != 0);
                }
                s[r][c] = ok ? val : -1e30f;
            }
        }

        // online softmax update
#pragma unroll
        for (int r = 0; r < 4; r++) {
            float rmax = fmaxf(fmaxf(s[r][0], s[r][1]), fmaxf(s[r][2], s[r][3]));
#pragma unroll
            for (int off = 8; off > 0; off >>= 1)
                rmax = fmaxf(rmax, __shfl_xor_sync(0xffffffffu, rmax, off));
            float mn = fmaxf(m[r], rmax);
            float corr = __expf(m[r] - mn);
            m[r] = mn;
            float rs = 0.f;
#pragma unroll
            for (int c = 0; c < 4; c++) {
                float p = __expf(s[r][c] - mn);
                s[r][c] = p; rs += p;
            }
#pragma unroll
            for (int off = 8; off > 0; off >>= 1)
                rs += __shfl_xor_sync(0xffffffffu, rs, off);
            lsum[r] = lsum[r] * corr + rs;
#pragma unroll
            for (int c = 0; c < 4; c++) acc[r][c] *= corr;
#pragma unroll
            for (int c = 0; c < 4; c++)
                Ss[(ty * 4 + r) * SPAD + tx * 4 + c] = s[r][c];
        }
        __syncthreads();

        // O += P @ V
#pragma unroll 4
        for (int jj = 0; jj < 64; jj++) {
            float pr[4];
#pragma unroll
            for (int r = 0; r < 4; r++) pr[r] = Ss[(ty * 4 + r) * SPAD + jj];
            float4 v4 = *(const float4*)&Vs[jj * SPAD + tx * 4];
            float vr[4] = { v4.x, v4.y, v4.z, v4.w };
#pragma unroll
            for (int r = 0; r < 4; r++)
#pragma unroll
                for (int c = 0; c < 4; c++)
                    acc[r][c] += pr[r] * vr[c];
        }
    }

    // write attention output, layout (b, n, h*dh)
#pragma unroll
    for (int r = 0; r < 4; r++) {
        int ig = i0 + ty * 4 + r;
        float invl = 1.0f / lsum[r];
        float* o = att + ((size_t)(b * N_ + ig)) * DIM_ + h * DH_ + tx * 4;
        float4 ov = { acc[r][0] * invl, acc[r][1] * invl,
                      acc[r][2] * invl, acc[r][3] * invl };
        *(float4*)o = ov;
    }
}

// ---------------- launch ----------------
extern "C" void kernel_launch(void* const* d_in, const int* in_sizes, int n_in,
                              void* d_out, int out_size) {
    const float* x     = (const float*)d_in[0];
    const int*   mask  = (const int*)d_in[1];        // bool promoted to int32 by harness
    const float* bias  = (const float*)d_in[2];
    const float* gamma = (const float*)d_in[3];
    const float* nkv   = (const float*)d_in[4];
    const float* Wq    = (const float*)d_in[5];
    const float* Wkv   = (const float*)d_in[6];
    const float* qsc   = (const float*)d_in[7];
    const float* ksc   = (const float*)d_in[8];
    const float* Wo    = (const float*)d_in[9];
    float* out = (float*)d_out;

    float *p_xn, *p_q, *p_kv, *p_Qn, *p_K, *p_V, *p_att;
    cudaGetSymbolAddress((void**)&p_xn,  g_xn);
    cudaGetSymbolAddress((void**)&p_q,   g_q);
    cudaGetSymbolAddress((void**)&p_kv,  g_kv);
    cudaGetSymbolAddress((void**)&p_Qn,  g_Qn);
    cudaGetSymbolAddress((void**)&p_K,   g_K);
    cudaGetSymbolAddress((void**)&p_V,   g_V);
    cudaGetSymbolAddress((void**)&p_att, g_att);

    // 1) layernorm
    ln_kernel<<<B_ * N_, 256>>>(x, gamma, p_xn);

    // 2) q = xn @ Wq  (4096x1024 @ 1024x1024)
    dim3 gq(DIM_ / 128, (B_ * N_) / 128);
    sgemm128<<<gq, 256>>>(p_xn, Wq, p_q, B_ * N_, DIM_, DIM_);

    // 3) kv = x @ Wkv (4096x1024 @ 1024x2048)  -- NOTE: un-normalized x
    dim3 gkv((2 * DIM_) / 128, (B_ * N_) / 128);
    sgemm128<<<gkv, 256>>>(x, Wkv, p_kv, B_ * N_, 2 * DIM_, DIM_);

    // 4) l2norm q/k, assemble K/V with null kv
    int nwarp = B_ * H_ * J_;
    prep_kernel<<<(nwarp + 7) / 8, 256>>>(p_q, p_kv, nkv, qsc, ksc, p_Qn, p_K, p_V);

    // 5) attention
    int smem = 4 * 64 * SPAD * (int)sizeof(float);
    cudaFuncSetAttribute(attn_kernel, cudaFuncAttributeMaxDynamicSharedMemorySize, smem);
    dim3 ga(N_ / 64, B_ * H_);
    attn_kernel<<<ga, 256, smem>>>(p_Qn, p_K, p_V, bias, mask, p_att);

    // 6) out = att @ Wo
    sgemm128<<<gq, 256>>>(p_att, Wo, out, B_ * N_, DIM_, DIM_);
}

// round 4
// speedup vs baseline: 1.2051x; 1.2051x over previous
#include <cuda_runtime.h>
#include <cuda_bf16.h>
#include <math.h>
#include <stdint.h>

// ---------------- problem constants ----------------
#define B_    2
#define N_    2048
#define DIM_  1024
#define H_    16
#define DH_   64
#define NNK_  2
#define J_    (N_ + NNK_)    // 2050
#define SCALE_ 8.0f
#define KP    3072           // split-K' = 3 * DIM_
#define MTOT  (B_ * N_)      // 4096

// ---------------- scratch (device globals; no allocs allowed) ----------------
__device__ __align__(16) __nv_bfloat16 g_x3   [MTOT * KP];      // [Ahi|Alo|Ahi] of x
__device__ __align__(16) __nv_bfloat16 g_xn3  [MTOT * KP];      // of layernorm(x)
__device__ __align__(16) __nv_bfloat16 g_att3 [MTOT * KP];      // of attention out
__device__ __align__(16) __nv_bfloat16 g_Wq3T [DIM_ * KP];      // [N=1024][Bhi|Bhi|Blo]
__device__ __align__(16) __nv_bfloat16 g_Wkv3T[2 * DIM_ * KP];  // [N=2048][...]
__device__ __align__(16) __nv_bfloat16 g_Wo3T [DIM_ * KP];
__device__ float g_q  [MTOT * DIM_];           // q projection (b,n,h*dh)
__device__ float g_kv [MTOT * 2 * DIM_];       // kv projection
__device__ float g_Qn [B_ * H_ * N_ * DH_];    // l2norm'd q, (b,h,n,d)
__device__ float g_K  [B_ * H_ * J_ * DH_];    // l2norm'd k incl nulls
__device__ float g_V  [B_ * H_ * J_ * DH_];    // v incl nulls

// ---------------- helpers ----------------
__device__ __forceinline__ void split_bf16(float v, __nv_bfloat16& hi, __nv_bfloat16& lo) {
    hi = __float2bfloat16_rn(v);
    lo = __float2bfloat16_rn(v - __bfloat162float(hi));
}

__device__ __forceinline__ void ldmx4(uint32_t* r, uint32_t addr) {
    asm volatile("ldmatrix.sync.aligned.m8n8.x4.shared.b16 {%0,%1,%2,%3}, [%4];"
                 : "=r"(r[0]), "=r"(r[1]), "=r"(r[2]), "=r"(r[3]) : "r"(addr));
}
__device__ __forceinline__ void ldmx2(uint32_t* r, uint32_t addr) {
    asm volatile("ldmatrix.sync.aligned.m8n8.x2.shared.b16 {%0,%1}, [%2];"
                 : "=r"(r[0]), "=r"(r[1]) : "r"(addr));
}
__device__ __forceinline__ void mma16816(float* d, const uint32_t* a, const uint32_t* b) {
    asm volatile("mma.sync.aligned.m16n8k16.row.col.f32.bf16.bf16.f32 {%0,%1,%2,%3},{%4,%5,%6,%7},{%8,%9},{%0,%1,%2,%3};"
                 : "+f"(d[0]), "+f"(d[1]), "+f"(d[2]), "+f"(d[3])
                 : "r"(a[0]), "r"(a[1]), "r"(a[2]), "r"(a[3]), "r"(b[0]), "r"(b[1]));
}

// ---------------- LayerNorm -> xn3 (A-side split layout) ----------------
__global__ void ln_kernel(const float* __restrict__ x,
                          const float* __restrict__ gamma,
                          __nv_bfloat16* __restrict__ xn3) {
    int row = blockIdx.x;
    const float* xr = x + (size_t)row * DIM_;
    float v[4];
    float s = 0.f, sq = 0.f;
#pragma unroll
    for (int i = 0; i < 4; i++) {
        float t = xr[threadIdx.x + i * 256];
        v[i] = t; s += t; sq += t * t;
    }
#pragma unroll
    for (int off = 16; off > 0; off >>= 1) {
        s  += __shfl_xor_sync(0xffffffffu, s,  off);
        sq += __shfl_xor_sync(0xffffffffu, sq, off);
    }
    __shared__ float sa[8], sb[8];
    int w = threadIdx.x >> 5, l = threadIdx.x & 31;
    if (l == 0) { sa[w] = s; sb[w] = sq; }
    __syncthreads();
    if (threadIdx.x == 0) {
        float a = 0.f, bq = 0.f;
#pragma unroll
        for (int i = 0; i < 8; i++) { a += sa[i]; bq += sb[i]; }
        sa[0] = a; sb[0] = bq;
    }
    __syncthreads();
    float mean = sa[0] * (1.0f / DIM_);
    float var  = sb[0] * (1.0f / DIM_) - mean * mean;
    float rstd = rsqrtf(var + 1e-5f);
    __nv_bfloat16* outr = xn3 + (size_t)row * KP;
#pragma unroll
    for (int i = 0; i < 4; i++) {
        int d = threadIdx.x + i * 256;
        float o = (v[i] - mean) * rstd * gamma[d];
        __nv_bfloat16 hi, lo; split_bf16(o, hi, lo);
        outr[d] = hi; outr[DIM_ + d] = lo; outr[2 * DIM_ + d] = hi;
    }
}

// ---------------- x -> x3 (A-side split) ----------------
__global__ void aconv_kernel(const float* __restrict__ X, __nv_bfloat16* __restrict__ X3) {
    int i = blockIdx.x * blockDim.x + threadIdx.x;
    if (i >= MTOT * DIM_) return;
    int r = i >> 10, c = i & (DIM_ - 1);
    float vv = X[i];
    __nv_bfloat16 hi, lo; split_bf16(vv, hi, lo);
    __nv_bfloat16* o = X3 + (size_t)r * KP;
    o[c] = hi; o[DIM_ + c] = lo; o[2 * DIM_ + c] = hi;
}

// ---------------- W [K=1024][N] -> W3T [N][KP] (B-side split, transposed) ----------------
__global__ void wconv_kernel(const float* __restrict__ W, __nv_bfloat16* __restrict__ W3T, int N) {
    __shared__ float t[32][33];
    int k0 = blockIdx.y * 32, n0 = blockIdx.x * 32;
    int tx = threadIdx.x, ty = threadIdx.y;   // 32 x 8
#pragma unroll
    for (int i = 0; i < 4; i++)
        t[ty + i * 8][tx] = W[(size_t)(k0 + ty + i * 8) * N + n0 + tx];
    __syncthreads();
#pragma unroll
    for (int i = 0; i < 4; i++) {
        int n = n0 + ty + i * 8;
        int k = k0 + tx;
        float w = t[tx][ty + i * 8];
        __nv_bfloat16 hi, lo; split_bf16(w, hi, lo);
        __nv_bfloat16* o = W3T + (size_t)n * KP;
        o[k] = hi; o[DIM_ + k] = hi; o[2 * DIM_ + k] = lo;
    }
}

// ---------------- bf16 HMMA GEMM: C[M,N] = A3[M,KP] @ B3T[N,KP]^T ----------------
#define BK 32
#define STRIDE 40
#define TSZ (128 * STRIDE)

__global__ void __launch_bounds__(256, 1) hgemm_kernel(
        const __nv_bfloat16* __restrict__ A,   // [M][KP]
        const __nv_bfloat16* __restrict__ BT,  // [N][KP]
        float* __restrict__ C, int M, int N) {
    __shared__ __nv_bfloat16 As[2 * TSZ];
    __shared__ __nv_bfloat16 Bs[2 * TSZ];

    const int tid  = threadIdx.x;
    const int wid  = tid >> 5, lane = tid & 31;
    const int wm   = wid & 1, wn = wid >> 1;      // warp tile 64(M) x 32(N)
    const int g    = lane >> 2, tig = lane & 3;

    const int row0 = blockIdx.y * 128;
    const int col0 = blockIdx.x * 128;

    // global loaders: 2 float4-rows per tile each
    const int lr = tid >> 2;              // 0..63
    const int lc = (tid & 3) * 8;         // 0,8,16,24
    const __nv_bfloat16* Ag = A  + (size_t)(row0 + lr) * KP + lc;
    const __nv_bfloat16* Bg = BT + (size_t)(col0 + lr) * KP + lc;

    float acc[4][4][4];
#pragma unroll
    for (int mi = 0; mi < 4; mi++)
#pragma unroll
        for (int ni = 0; ni < 4; ni++)
#pragma unroll
            for (int e = 0; e < 4; e++) acc[mi][ni][e] = 0.f;

    uint32_t a_base = (uint32_t)__cvta_generic_to_shared(As);
    uint32_t b_base = (uint32_t)__cvta_generic_to_shared(Bs);

    // ldmatrix per-lane offsets (elements)
    const int a_row_in = lane & 15;             // row within 16
    const int a_k_in   = (lane >> 4) << 3;      // 0 or 8
    const int b_row_in = lane & 7;
    const int b_k_in   = ((lane >> 3) & 1) << 3;

    // preload stage 0
    {
        uint4 ra0 = *(const uint4*)(Ag);
        uint4 ra1 = *(const uint4*)(Ag + (size_t)64 * KP);
        uint4 rb0 = *(const uint4*)(Bg);
        uint4 rb1 = *(const uint4*)(Bg + (size_t)64 * KP);
        *(uint4*)&As[lr * STRIDE + lc]        = ra0;
        *(uint4*)&As[(lr + 64) * STRIDE + lc] = ra1;
        *(uint4*)&Bs[lr * STRIDE + lc]        = rb0;
        *(uint4*)&Bs[(lr + 64) * STRIDE + lc] = rb1;
    }
    __syncthreads();

    int buf = 0;
    for (int kt = 0; kt < KP; kt += BK) {
        const bool has_next = (kt + BK) < KP;
        uint4 ra0, ra1, rb0, rb1;
        if (has_next) {
            ra0 = *(const uint4*)(Ag + kt + BK);
            ra1 = *(const uint4*)(Ag + (size_t)64 * KP + kt + BK);
            rb0 = *(const uint4*)(Bg + kt + BK);
            rb1 = *(const uint4*)(Bg + (size_t)64 * KP + kt + BK);
        }

        const uint32_t abuf = a_base + buf * (TSZ * 2);
        const uint32_t bbuf = b_base + buf * (TSZ * 2);
#pragma unroll
        for (int kk = 0; kk < BK; kk += 16) {
            uint32_t afr[4][4];
            uint32_t bfr[4][2];
#pragma unroll
            for (int mi = 0; mi < 4; mi++) {
                uint32_t a_addr = abuf +
                    (uint32_t)(((wm * 64 + mi * 16 + a_row_in) * STRIDE + kk + a_k_in) << 1);
                ldmx4(afr[mi], a_addr);
            }
#pragma unroll
            for (int ni = 0; ni < 4; ni++) {
                uint32_t b_addr = bbuf +
                    (uint32_t)(((wn * 32 + ni * 8 + b_row_in) * STRIDE + kk + b_k_in) << 1);
                ldmx2(bfr[ni], b_addr);
            }
#pragma unroll
            for (int mi = 0; mi < 4; mi++)
#pragma unroll
                for (int ni = 0; ni < 4; ni++)
                    mma16816(acc[mi][ni], afr[mi], bfr[ni]);
        }

        if (has_next) {
            __nv_bfloat16* as = &As[(buf ^ 1) * TSZ];
            __nv_bfloat16* bs = &Bs[(buf ^ 1) * TSZ];
            *(uint4*)&as[lr * STRIDE + lc]        = ra0;
            *(uint4*)&as[(lr + 64) * STRIDE + lc] = ra1;
            *(uint4*)&bs[lr * STRIDE + lc]        = rb0;
            *(uint4*)&bs[(lr + 64) * STRIDE + lc] = rb1;
            __syncthreads();
            buf ^= 1;
        }
    }

    // epilogue
#pragma unroll
    for (int mi = 0; mi < 4; mi++) {
        int r0 = row0 + wm * 64 + mi * 16 + g;
#pragma unroll
        for (int ni = 0; ni < 4; ni++) {
            int cc = col0 + wn * 32 + ni * 8 + tig * 2;
            float2 v0 = { acc[mi][ni][0], acc[mi][ni][1] };
            float2 v1 = { acc[mi][ni][2], acc[mi][ni][3] };
            *(float2*)&C[(size_t)r0 * N + cc]       = v0;
            *(float2*)&C[(size_t)(r0 + 8) * N + cc] = v1;
        }
    }
}

// ---------------- prep: build Qn (l2norm*q_scale), K (nulls + l2norm*k_scale), V ----------------
__global__ void prep_kernel(const float* __restrict__ q,
                            const float* __restrict__ kv,
                            const float* __restrict__ null_kv,
                            const float* __restrict__ q_scale,
                            const float* __restrict__ k_scale,
                            float* __restrict__ Qn,
                            float* __restrict__ Kk,
                            float* __restrict__ Vv) {
    int warp = (blockIdx.x * blockDim.x + threadIdx.x) >> 5;
    int lane = threadIdx.x & 31;
    if (warp >= B_ * H_ * J_) return;
    int bh = warp / J_;
    int j  = warp % J_;
    int b = bh / H_, h = bh % H_;
    int d0 = lane, d1 = lane + 32;

    float k0, k1, v0, v1;
    if (j < NNK_) {
        const float* nb = null_kv + ((size_t)(h * NNK_ + j) * 2) * DH_;
        k0 = nb[d0];        k1 = nb[d1];
        v0 = nb[DH_ + d0];  v1 = nb[DH_ + d1];
    } else {
        int n = j - NNK_;
        const float* base = kv + ((size_t)(b * N_ + n)) * (2 * DIM_) + h * DH_;
        k0 = base[d0];          k1 = base[d1];
        v0 = base[DIM_ + d0];   v1 = base[DIM_ + d1];
    }
    float ss = k0 * k0 + k1 * k1;
#pragma unroll
    for (int off = 16; off > 0; off >>= 1)
        ss += __shfl_xor_sync(0xffffffffu, ss, off);
    float inv = 1.0f / fmaxf(sqrtf(ss), 1e-12f);
    size_t kvo = ((size_t)bh * J_ + j) * DH_;
    Kk[kvo + d0] = k0 * inv * k_scale[d0];
    Kk[kvo + d1] = k1 * inv * k_scale[d1];
    Vv[kvo + d0] = v0;
    Vv[kvo + d1] = v1;

    if (j < N_) {
        int n = j;
        const float* qb = q + ((size_t)(b * N_ + n)) * DIM_ + h * DH_;
        float a0 = qb[d0], a1 = qb[d1];
        float qs2 = a0 * a0 + a1 * a1;
#pragma unroll
        for (int off = 16; off > 0; off >>= 1)
            qs2 += __shfl_xor_sync(0xffffffffu, qs2, off);
        float qinv = 1.0f / fmaxf(sqrtf(qs2), 1e-12f);
        size_t qo = ((size_t)bh * N_ + n) * DH_;
        Qn[qo + d0] = a0 * qinv * q_scale[d0];
        Qn[qo + d1] = a1 * qinv * q_scale[d1];
    }
}

// ---------------- flash attention: 64x64 tiles, online softmax, causal skip ----------------
#define SPAD 68
__global__ void __launch_bounds__(256) attn_kernel(
        const float* __restrict__ Qn, const float* __restrict__ Kk,
        const float* __restrict__ Vv, const float* __restrict__ bias,
        const int* __restrict__ mask,
        __nv_bfloat16* __restrict__ att3) {
    extern __shared__ float sh[];
    float* Qs  = sh;
    float* KsT = Qs  + 64 * SPAD;
    float* Vs  = KsT + 64 * SPAD;
    float* Ss  = Vs  + 64 * SPAD;

    const int tid = threadIdx.x;
    const int tx = tid & 15, ty = tid >> 4;
    const int ib = blockIdx.x;
    const int bh = blockIdx.y;
    const int b = bh >> 4, h = bh & 15;
    const int i0 = ib * 64;

    const float* Qbase = Qn + ((size_t)bh * N_ + i0) * DH_;
#pragma unroll
    for (int fi = tid; fi < 64 * 16; fi += 256) {
        int r = fi >> 4, c4 = (fi & 15) << 2;
        *(float4*)&Qs[r * SPAD + c4] = *(const float4*)(Qbase + (size_t)r * DH_ + c4);
    }

    float m[4], lsum[4], acc[4][4];
#pragma unroll
    for (int r = 0; r < 4; r++) {
        m[r] = -1e30f; lsum[r] = 0.f;
#pragma unroll
        for (int c = 0; c < 4; c++) acc[r][c] = 0.f;
    }

    const int jt_max = min(ib + 1, (J_ + 63) / 64 - 1);

    for (int jt = 0; jt <= jt_max; jt++) {
        const int j0 = jt * 64;
        __syncthreads();
        for (int fi = tid; fi < 64 * 16; fi += 256) {
            int r = fi >> 4, c4 = (fi & 15) << 2;
            int j = j0 + r;
            if (j < J_) {
                float4 k4 = *(const float4*)(Kk + ((size_t)bh * J_ + j) * DH_ + c4);
                KsT[(c4 + 0) * SPAD + r] = k4.x;
                KsT[(c4 + 1) * SPAD + r] = k4.y;
                KsT[(c4 + 2) * SPAD + r] = k4.z;
                KsT[(c4 + 3) * SPAD + r] = k4.w;
                *(float4*)&Vs[r * SPAD + c4] =
                    *(const float4*)(Vv + ((size_t)bh * J_ + j) * DH_ + c4);
            } else {
                KsT[(c4 + 0) * SPAD + r] = 0.f;
                KsT[(c4 + 1) * SPAD + r] = 0.f;
                KsT[(c4 + 2) * SPAD + r] = 0.f;
                KsT[(c4 + 3) * SPAD + r] = 0.f;
                float4 z = {0.f, 0.f, 0.f, 0.f};
                *(float4*)&Vs[r * SPAD + c4] = z;
            }
        }
        __syncthreads();

        float s[4][4];
#pragma unroll
        for (int r = 0; r < 4; r++)
#pragma unroll
            for (int c = 0; c < 4; c++) s[r][c] = 0.f;

#pragma unroll 4
        for (int d = 0; d < 64; d++) {
            float qr[4];
#pragma unroll
            for (int r = 0; r < 4; r++) qr[r] = Qs[(ty * 4 + r) * SPAD + d];
            float4 k4 = *(const float4*)&KsT[d * SPAD + tx * 4];
            float kr[4] = { k4.x, k4.y, k4.z, k4.w };
#pragma unroll
            for (int r = 0; r < 4; r++)
#pragma unroll
                for (int c = 0; c < 4; c++)
                    s[r][c] += qr[r] * kr[c];
        }

#pragma unroll
        for (int r = 0; r < 4; r++) {
            int ig = i0 + ty * 4 + r;
#pragma unroll
            for (int c = 0; c < 4; c++) {
                int jg = j0 + tx * 4 + c;
                float val = s[r][c] * SCALE_;
                bool ok = (jg < J_) && (jg <= ig + NNK_);
                if (jg >= NNK_ && ok) {
                    val += bias[((size_t)h * N_ + ig) * N_ + (jg - NNK_)];
                    ok = (mask[b * N_ + jg - NNK_] != 0);
                }
                s[r][c] = ok ? val : -1e30f;
            }
        }

#pragma unroll
        for (int r = 0; r < 4; r++) {
            float rmax = fmaxf(fmaxf(s[r][0], s[r][1]), fmaxf(s[r][2], s[r][3]));
#pragma unroll
            for (int off = 8; off > 0; off >>= 1)
                rmax = fmaxf(rmax, __shfl_xor_sync(0xffffffffu, rmax, off));
            float mn = fmaxf(m[r], rmax);
            float corr = __expf(m[r] - mn);
            m[r] = mn;
            float rs = 0.f;
#pragma unroll
            for (int c = 0; c < 4; c++) {
                float p = __expf(s[r][c] - mn);
                s[r][c] = p; rs += p;
            }
#pragma unroll
            for (int off = 8; off > 0; off >>= 1)
                rs += __shfl_xor_sync(0xffffffffu, rs, off);
            lsum[r] = lsum[r] * corr + rs;
#pragma unroll
            for (int c = 0; c < 4; c++) acc[r][c] *= corr;
#pragma unroll
            for (int c = 0; c < 4; c++)
                Ss[(ty * 4 + r) * SPAD + tx * 4 + c] = s[r][c];
        }
        __syncthreads();

#pragma unroll 4
        for (int jj = 0; jj < 64; jj++) {
            float pr[4];
#pragma unroll
            for (int r = 0; r < 4; r++) pr[r] = Ss[(ty * 4 + r) * SPAD + jj];
            float4 v4 = *(const float4*)&Vs[jj * SPAD + tx * 4];
            float vr[4] = { v4.x, v4.y, v4.z, v4.w };
#pragma unroll
            for (int r = 0; r < 4; r++)
#pragma unroll
                for (int c = 0; c < 4; c++)
                    acc[r][c] += pr[r] * vr[c];
        }
    }

    // write attention output into A-side split layout [row][KP]
#pragma unroll
    for (int r = 0; r < 4; r++) {
        int ig = i0 + ty * 4 + r;
        float invl = 1.0f / lsum[r];
        __nv_bfloat16* o3 = att3 + ((size_t)(b * N_ + ig)) * KP + h * DH_ + tx * 4;
        __nv_bfloat16 hi[4], lo[4];
#pragma unroll
        for (int c = 0; c < 4; c++) split_bf16(acc[r][c] * invl, hi[c], lo[c]);
        *(__nv_bfloat162*)&o3[0]            = __halves2bfloat162(hi[0], hi[1]);
        *(__nv_bfloat162*)&o3[2]            = __halves2bfloat162(hi[2], hi[3]);
        *(__nv_bfloat162*)&o3[DIM_]         = __halves2bfloat162(lo[0], lo[1]);
        *(__nv_bfloat162*)&o3[DIM_ + 2]     = __halves2bfloat162(lo[2], lo[3]);
        *(__nv_bfloat162*)&o3[2 * DIM_]     = __halves2bfloat162(hi[0], hi[1]);
        *(__nv_bfloat162*)&o3[2 * DIM_ + 2] = __halves2bfloat162(hi[2], hi[3]);
    }
}

// ---------------- launch ----------------
extern "C" void kernel_launch(void* const* d_in, const int* in_sizes, int n_in,
                              void* d_out, int out_size) {
    const float* x     = (const float*)d_in[0];
    const int*   mask  = (const int*)d_in[1];
    const float* bias  = (const float*)d_in[2];
    const float* gamma = (const float*)d_in[3];
    const float* nkv   = (const float*)d_in[4];
    const float* Wq    = (const float*)d_in[5];
    const float* Wkv   = (const float*)d_in[6];
    const float* qsc   = (const float*)d_in[7];
    const float* ksc   = (const float*)d_in[8];
    const float* Wo    = (const float*)d_in[9];
    float* out = (float*)d_out;

    __nv_bfloat16 *p_x3, *p_xn3, *p_att3, *p_Wq3T, *p_Wkv3T, *p_Wo3T;
    float *p_q, *p_kv, *p_Qn, *p_K, *p_V;
    cudaGetSymbolAddress((void**)&p_x3,    g_x3);
    cudaGetSymbolAddress((void**)&p_xn3,   g_xn3);
    cudaGetSymbolAddress((void**)&p_att3,  g_att3);
    cudaGetSymbolAddress((void**)&p_Wq3T,  g_Wq3T);
    cudaGetSymbolAddress((void**)&p_Wkv3T, g_Wkv3T);
    cudaGetSymbolAddress((void**)&p_Wo3T,  g_Wo3T);
    cudaGetSymbolAddress((void**)&p_q,     g_q);
    cudaGetSymbolAddress((void**)&p_kv,    g_kv);
    cudaGetSymbolAddress((void**)&p_Qn,    g_Qn);
    cudaGetSymbolAddress((void**)&p_K,     g_K);
    cudaGetSymbolAddress((void**)&p_V,     g_V);

    // weight conversions (transpose + hi/lo split)
    dim3 wb(32, 8);
    wconv_kernel<<<dim3(DIM_ / 32,     DIM_ / 32), wb>>>(Wq,  p_Wq3T,  DIM_);
    wconv_kernel<<<dim3(2 * DIM_ / 32, DIM_ / 32), wb>>>(Wkv, p_Wkv3T, 2 * DIM_);
    wconv_kernel<<<dim3(DIM_ / 32,     DIM_ / 32), wb>>>(Wo,  p_Wo3T,  DIM_);

    // activation conversions
    aconv_kernel<<<(MTOT * DIM_ + 255) / 256, 256>>>(x, p_x3);
    ln_kernel<<<MTOT, 256>>>(x, gamma, p_xn3);

    // projections via bf16-split HMMA
    dim3 gq(DIM_ / 128, MTOT / 128);
    hgemm_kernel<<<gq, 256>>>(p_xn3, p_Wq3T, p_q, MTOT, DIM_);
    dim3 gkv(2 * DIM_ / 128, MTOT / 128);
    hgemm_kernel<<<gkv, 256>>>(p_x3, p_Wkv3T, p_kv, MTOT, 2 * DIM_);

    // l2norm q/k, assemble K/V with null kv
    int nwarp = B_ * H_ * J_;
    prep_kernel<<<(nwarp + 7) / 8, 256>>>(p_q, p_kv, nkv, qsc, ksc, p_Qn, p_K, p_V);

    // attention (emits split layout directly)
    int smem = 4 * 64 * SPAD * (int)sizeof(float);
    cudaFuncSetAttribute(attn_kernel, cudaFuncAttributeMaxDynamicSharedMemorySize, smem);
    dim3 ga(N_ / 64, B_ * H_);
    attn_kernel<<<ga, 256, smem>>>(p_Qn, p_K, p_V, bias, mask, p_att3);

    // output projection
    hgemm_kernel<<<gq, 256>>>(p_att3, p_Wo3T, out, MTOT, DIM_);
}